// round 12
// baseline (speedup 1.0000x reference)
#include <cuda_runtime.h>
#include <cuda_bf16.h>
#include <cstdint>

#define B_   64
#define NN_  64
#define HL_  50
#define IN_  384
#define POS_ 64
#define ATT_ 256
#define NEWS_ 448
#define W1COLS_ 896

// Scratch
__device__ float g_pn[B_ * NN_ * ATT_];
__device__ float g_pl[B_ * HL_ * ATT_];

__device__ __forceinline__ float tanh_fast(float x) {
    float y; asm("tanh.approx.f32 %0, %1;" : "=f"(y) : "f"(x)); return y;
}
__device__ __forceinline__ uint32_t to_tf32(float f) {
    uint32_t r; asm("cvt.rna.tf32.f32 %0, %1;" : "=r"(r) : "f"(f)); return r;
}
__device__ __forceinline__ void mma_tf32(float* c, const uint32_t* a, const uint32_t* b) {
    asm volatile(
        "mma.sync.aligned.m16n8k8.row.col.f32.tf32.tf32.f32 "
        "{%0,%1,%2,%3}, {%4,%5,%6,%7}, {%8,%9}, {%0,%1,%2,%3};"
        : "+f"(c[0]), "+f"(c[1]), "+f"(c[2]), "+f"(c[3])
        : "r"(a[0]), "r"(a[1]), "r"(a[2]), "r"(a[3]), "r"(b[0]), "r"(b[1]));
}

// ---------------------------------------------------------------------------
// Kernel B: mma.sync tf32 GEMM, FULL K=448 (pos tiles from pos_emb) (unchanged)
// ---------------------------------------------------------------------------
#define BK 32
#define LDT 36
#define NKT (NEWS_ / BK)   // 14

__global__ __launch_bounds__(256) void gemm_mma_kernel(
    const float* __restrict__ news_vec,
    const float* __restrict__ log_vec,
    const float* __restrict__ pos_emb,
    const float* __restrict__ b1,
    const float* __restrict__ W1)
{
    __shared__ uint32_t As[128 * LDT];
    __shared__ uint32_t Ws[128 * LDT];

    int tid  = threadIdx.x;
    int wid  = tid >> 5, lane = tid & 31;
    int gid  = lane >> 2, tig = lane & 3;
    int wm   = wid & 1;
    int wn   = wid >> 1;

    int bx   = blockIdx.x;
    int nh   = bx & 1;
    int tile = bx >> 1;
    int mode, mtile, w_off;
    const float* A;
    if (tile < 32) { mode = 0; mtile = tile;      A = news_vec; w_off = 0; }
    else           { mode = 1; mtile = tile - 32; A = log_vec;  w_off = NEWS_; }
    int n_base = nh * 128;

    int lrow = tid >> 3;
    int lf4  = tid & 7;
    const float* Abase = A  + (size_t)(mtile * 128 + lrow) * IN_ + lf4 * 4;
    const float* Wbase = W1 + (size_t)(n_base + lrow) * W1COLS_ + w_off + lf4 * 4;

    const float* posA[4];
    #pragma unroll
    for (int p = 0; p < 4; p++) {
        if (mode == 0) {
            posA[p] = pos_emb + lf4 * 4;
        } else {
            int r = mtile * 128 + p * 32 + lrow;
            posA[p] = pos_emb + (size_t)(1 + (r % HL_)) * POS_ + lf4 * 4;
        }
    }

    float acc[4][4][4];
    #pragma unroll
    for (int i = 0; i < 4; i++)
        #pragma unroll
        for (int j = 0; j < 4; j++)
            #pragma unroll
            for (int k = 0; k < 4; k++) acc[i][j][k] = 0.f;

    float4 aReg[4], wReg[4];
    #pragma unroll
    for (int p = 0; p < 4; p++) {
        aReg[p] = *(const float4*)(Abase + (size_t)p * 32 * IN_);
        wReg[p] = *(const float4*)(Wbase + (size_t)p * 32 * W1COLS_);
    }

    for (int kt = 0; kt < NKT; kt++) {
        #pragma unroll
        for (int p = 0; p < 4; p++) {
            uint32_t* as = &As[(p * 32 + lrow) * LDT + lf4 * 4];
            as[0] = to_tf32(aReg[p].x); as[1] = to_tf32(aReg[p].y);
            as[2] = to_tf32(aReg[p].z); as[3] = to_tf32(aReg[p].w);
            uint32_t* ws = &Ws[(p * 32 + lrow) * LDT + lf4 * 4];
            ws[0] = to_tf32(wReg[p].x); ws[1] = to_tf32(wReg[p].y);
            ws[2] = to_tf32(wReg[p].z); ws[3] = to_tf32(wReg[p].w);
        }
        __syncthreads();

        if (kt + 1 < NKT) {
            int t = kt + 1;
            if (t < IN_ / BK) {
                const float* An = Abase + t * BK;
                #pragma unroll
                for (int p = 0; p < 4; p++)
                    aReg[p] = *(const float4*)(An + (size_t)p * 32 * IN_);
            } else {
                int off = (t - IN_ / BK) * BK;
                #pragma unroll
                for (int p = 0; p < 4; p++)
                    aReg[p] = *(const float4*)(posA[p] + off);
            }
            const float* Wn = Wbase + t * BK;
            #pragma unroll
            for (int p = 0; p < 4; p++)
                wReg[p] = *(const float4*)(Wn + (size_t)p * 32 * W1COLS_);
        }

        #pragma unroll
        for (int kk = 0; kk < BK; kk += 8) {
            uint32_t afr[4][4], bfr[4][2];
            #pragma unroll
            for (int mf = 0; mf < 4; mf++) {
                int r0 = (wm * 64 + mf * 16 + gid) * LDT + kk + tig;
                afr[mf][0] = As[r0];
                afr[mf][1] = As[r0 + 8 * LDT];
                afr[mf][2] = As[r0 + 4];
                afr[mf][3] = As[r0 + 8 * LDT + 4];
            }
            #pragma unroll
            for (int nf = 0; nf < 4; nf++) {
                int c0 = (wn * 32 + nf * 8 + gid) * LDT + kk + tig;
                bfr[nf][0] = Ws[c0];
                bfr[nf][1] = Ws[c0 + 4];
            }
            #pragma unroll
            for (int mf = 0; mf < 4; mf++)
                #pragma unroll
                for (int nf = 0; nf < 4; nf++)
                    mma_tf32(acc[mf][nf], afr[mf], bfr[nf]);
        }
        __syncthreads();
    }

    float* outp = (mode == 0) ? g_pn : g_pl;
    #pragma unroll
    for (int mf = 0; mf < 4; mf++) {
        int r0 = mtile * 128 + wm * 64 + mf * 16 + gid;
        int r1 = r0 + 8;
        #pragma unroll
        for (int nf = 0; nf < 4; nf++) {
            int c = n_base + wn * 32 + nf * 8 + 2 * tig;
            float bx0 = 0.f, bx1 = 0.f;
            if (mode == 0) { bx0 = b1[c]; bx1 = b1[c + 1]; }
            float2 v0, v1;
            v0.x = acc[mf][nf][0] + bx0;
            v0.y = acc[mf][nf][1] + bx1;
            v1.x = acc[mf][nf][2] + bx0;
            v1.y = acc[mf][nf][3] + bx1;
            *(float2*)(outp + (size_t)r0 * ATT_ + c) = v0;
            *(float2*)(outp + (size_t)r1 * ATT_ + c) = v1;
        }
    }
}

// ---------------------------------------------------------------------------
// Kernel C: FUSED mask-compact + balanced attn + out. Block = (b, quarter).
// Phase B: flattened (n, j-pair) queue split into 14 equal contiguous chunks;
// raw logits deposited to smem; separate cheap softmax pass.
// ---------------------------------------------------------------------------
#define FUSE_SMEM ((50 * 256 + 16 * 52 + 64 + 4) * 4)
__global__ __launch_bounds__(448, 2) void fused_kernel(
    const float* __restrict__ log_vec,
    const float* __restrict__ news_vec,
    const float* __restrict__ pos_emb,
    const int*   __restrict__ log_mask,
    const float* __restrict__ W2,
    const float* __restrict__ b2,
    float* __restrict__ out,
    float* __restrict__ nf_out)
{
    extern __shared__ float sm[];
    float* pl_s   = sm;                        // 50*256
    float* attn_s = sm + 50 * 256;             // 16*52 (logits, then attn)
    int*   act_s  = (int*)(sm + 50 * 256 + 16 * 52);   // 52 (padded 64)
    int*   meta_s = act_s + 64;                 // cnt, unif

    int tid  = threadIdx.x;
    int b    = blockIdx.x >> 2;
    int q    = blockIdx.x & 3;
    int warp = tid >> 5, lane = tid & 31;

    // mask compaction (warp 0, ballots)
    if (warp == 0) {
        int m1 = log_mask[b * HL_ + lane] != 0;
        int m2 = (lane < HL_ - 32) ? (log_mask[b * HL_ + 32 + lane] != 0) : 0;
        unsigned bb0 = __ballot_sync(0xffffffffu, m1);
        unsigned bb1 = __ballot_sync(0xffffffffu, m2);
        int cnt = __popc(bb0) + __popc(bb1);
        if (cnt == 0) {
            act_s[lane] = lane;
            if (lane < HL_ - 32) act_s[32 + lane] = 32 + lane;
            if (lane == 0) { meta_s[0] = HL_; meta_s[1] = 1; }
        } else {
            if (m1) act_s[__popc(bb0 & ((1u << lane) - 1u))] = lane;
            if (m2) act_s[__popc(bb0) + __popc(bb1 & ((1u << lane) - 1u))] = 32 + lane;
            if (lane == 0) { meta_s[0] = cnt; meta_s[1] = 0; }
        }
    }
    __syncthreads();
    int cnt  = meta_s[0];
    int unif = meta_s[1];

    // stage compact pl
    {
        int npl = cnt * 64;
        const float4* plg = (const float4*)(g_pl + (size_t)b * HL_ * ATT_);
        for (int i = tid; i < npl; i += 448) {
            int j = i >> 6, r = i & 63;
            ((float4*)pl_s)[j * 64 + r] = plg[(size_t)act_s[j] * 64 + r];
        }
    }
    float w2r[8];
    #pragma unroll
    for (int k = 0; k < 8; k++) w2r[k] = W2[lane + 32 * k];
    float bias2 = b2[0];
    __syncthreads();

    // ---- Phase B1: balanced logit queue -> raw logits in attn_s ----
    if (!unif) {
        int jpairs = (cnt + 1) >> 1;
        int nitems = 16 * jpairs;
        int chunk  = (nitems + 13) / 14;
        int st = warp * chunk;
        int en = st + chunk; if (en > nitems) en = nitems;

        int   cur_n = -1;
        float pnr[8];
        for (int it = st; it < en; it++) {
            int nn = it / jpairs;
            int jp = it - nn * jpairs;
            if (nn != cur_n) {
                int bn = b * NN_ + q * 16 + nn;
                #pragma unroll
                for (int k = 0; k < 8; k++)
                    pnr[k] = g_pn[(size_t)bn * ATT_ + lane + 32 * k];
                cur_n = nn;
            }
            int jj = jp * 2;
            bool two = (jj + 1 < cnt);
            const float* p0 = pl_s + jj * ATT_;
            const float* p1 = pl_s + (two ? jj + 1 : jj) * ATT_;
            float s0 = 0.f, s1 = 0.f;
            #pragma unroll
            for (int k = 0; k < 8; k++) {
                float pk = pnr[k];
                s0 += tanh_fast(pk + p0[lane + 32 * k]) * w2r[k];
                s1 += tanh_fast(pk + p1[lane + 32 * k]) * w2r[k];
            }
            #pragma unroll
            for (int o = 16; o > 0; o >>= 1) {
                s0 += __shfl_xor_sync(0xffffffffu, s0, o);
                s1 += __shfl_xor_sync(0xffffffffu, s1, o);
            }
            if (lane == 0) {
                float* arow = attn_s + nn * 52;
                arow[jj] = s0 + bias2;
                if (two) arow[jj + 1] = s1 + bias2;
            }
        }
    }
    __syncthreads();

    // ---- Phase B2: softmax in place (1 warp per n) ----
    for (int nn = warp; nn < 16; nn += 14) {
        float* arow = attn_s + nn * 52;
        if (!unif) {
            float v0 = (lane < cnt)      ? arow[lane]      : -3.0e38f;
            float v1 = (lane + 32 < cnt) ? arow[lane + 32] : -3.0e38f;
            float mx = fmaxf(v0, v1);
            #pragma unroll
            for (int o = 16; o > 0; o >>= 1)
                mx = fmaxf(mx, __shfl_xor_sync(0xffffffffu, mx, o));
            float e0 = __expf(v0 - mx), e1 = __expf(v1 - mx);
            float sv = e0 + e1;
            #pragma unroll
            for (int o = 16; o > 0; o >>= 1)
                sv += __shfl_xor_sync(0xffffffffu, sv, o);
            float inv = 1.f / sv;
            arow[lane] = (lane < cnt) ? e0 * inv : 0.f;
            if (lane < 20) arow[lane + 32] = (lane + 32 < cnt) ? e1 * inv : 0.f;
        } else {
            float u = 1.f / HL_;
            arow[lane] = (lane < cnt) ? u : 0.f;
            if (lane < 20) arow[lane + 32] = (lane + 32 < cnt) ? u : 0.f;
        }
    }
    __syncthreads();

    // ---- Phase C: lf gather (spill-free) + weighted sum ----
    int d = tid;   // 0..447
    float lf_reg[52];
    {
        const float* lv = log_vec + (size_t)b * HL_ * IN_ + d;
        const float* pe = pos_emb + POS_ + (d - IN_);
        bool lowd = (d < IN_);
        #pragma unroll
        for (int j = 0; j < 52; j++) {
            float v = 0.f;
            if (j < cnt) {
                int h = act_s[j];
                v = lowd ? lv[(size_t)h * IN_] : pe[(size_t)h * POS_];
            }
            lf_reg[j] = v;
        }
    }

    {
        const float4* at4 = (const float4*)attn_s;
        float* obase = out + ((size_t)(b * NN_ + q * 16)) * NEWS_ + d;
        #pragma unroll 4
        for (int i = 0; i < 16; i++) {
            float4 a4acc = make_float4(0.f, 0.f, 0.f, 0.f);
            #pragma unroll
            for (int k = 0; k < 13; k++) {
                float4 a4 = at4[i * 13 + k];
                a4acc.x += a4.x * lf_reg[4 * k];
                a4acc.y += a4.y * lf_reg[4 * k + 1];
                a4acc.z += a4.z * lf_reg[4 * k + 2];
                a4acc.w += a4.w * lf_reg[4 * k + 3];
            }
            obase[(size_t)i * NEWS_] = (a4acc.x + a4acc.y) + (a4acc.z + a4acc.w);
        }
    }

    // nf for this block's 16 rows
    {
        int rbase = b * NN_ + q * 16;
        bool lowd = (d < IN_);
        float posv = lowd ? 0.f : pos_emb[d - IN_];
        #pragma unroll 4
        for (int r = 0; r < 16; r++) {
            int gr = rbase + r;
            nf_out[(size_t)gr * NEWS_ + d] =
                lowd ? news_vec[(size_t)gr * IN_ + d] : posv;
        }
    }
}

// ---------------------------------------------------------------------------
extern "C" void kernel_launch(void* const* d_in, const int* in_sizes, int n_in,
                              void* d_out, int out_size)
{
    const float* log_vec  = (const float*)d_in[0];
    const int*   log_mask = (const int*)  d_in[1];
    const float* news_vec = (const float*)d_in[2];
    const float* pos_emb  = (const float*)d_in[3];
    const float* W1       = (const float*)d_in[4];
    const float* b1       = (const float*)d_in[5];
    const float* W2       = (const float*)d_in[6];
    const float* b2       = (const float*)d_in[7];
    float* out = (float*)d_out;

    const int NF_TOTAL = B_ * NN_ * NEWS_;
    cudaFuncSetAttribute(fused_kernel, cudaFuncAttributeMaxDynamicSharedMemorySize, FUSE_SMEM);

    gemm_mma_kernel<<<114, 256>>>(news_vec, log_vec, pos_emb, b1, W1);
    fused_kernel<<<B_ * 4, 448, FUSE_SMEM>>>(log_vec, news_vec, pos_emb, log_mask,
                                             W2, b2, out, out + NF_TOTAL);
}

// round 14
// speedup vs baseline: 1.1047x; 1.1047x over previous
#include <cuda_runtime.h>
#include <cuda_bf16.h>
#include <cstdint>

#define B_   64
#define NN_  64
#define HL_  50
#define IN_  384
#define POS_ 64
#define ATT_ 256
#define NEWS_ 448
#define W1COLS_ 896

// Scratch
__device__ float g_pn[B_ * NN_ * ATT_];
__device__ float g_pl[B_ * HL_ * ATT_];

__device__ __forceinline__ float tanh_fast(float x) {
    float y; asm("tanh.approx.f32 %0, %1;" : "=f"(y) : "f"(x)); return y;
}
__device__ __forceinline__ uint32_t to_tf32(float f) {
    uint32_t r; asm("cvt.rna.tf32.f32 %0, %1;" : "=r"(r) : "f"(f)); return r;
}
__device__ __forceinline__ void mma_tf32(float* c, const uint32_t* a, const uint32_t* b) {
    asm volatile(
        "mma.sync.aligned.m16n8k8.row.col.f32.tf32.tf32.f32 "
        "{%0,%1,%2,%3}, {%4,%5,%6,%7}, {%8,%9}, {%0,%1,%2,%3};"
        : "+f"(c[0]), "+f"(c[1]), "+f"(c[2]), "+f"(c[3])
        : "r"(a[0]), "r"(a[1]), "r"(a[2]), "r"(a[3]), "r"(b[0]), "r"(b[1]));
}

// ---------------------------------------------------------------------------
// Kernel B: mma.sync tf32 GEMM, FULL K=448 (pos tiles from pos_emb)
// ---------------------------------------------------------------------------
#define BK 32
#define LDT 36
#define NKT (NEWS_ / BK)   // 14

__global__ __launch_bounds__(256) void gemm_mma_kernel(
    const float* __restrict__ news_vec,
    const float* __restrict__ log_vec,
    const float* __restrict__ pos_emb,
    const float* __restrict__ b1,
    const float* __restrict__ W1)
{
    __shared__ uint32_t As[128 * LDT];
    __shared__ uint32_t Ws[128 * LDT];

    int tid  = threadIdx.x;
    int wid  = tid >> 5, lane = tid & 31;
    int gid  = lane >> 2, tig = lane & 3;
    int wm   = wid & 1;
    int wn   = wid >> 1;

    int bx   = blockIdx.x;
    int nh   = bx & 1;
    int tile = bx >> 1;
    int mode, mtile, w_off;
    const float* A;
    if (tile < 32) { mode = 0; mtile = tile;      A = news_vec; w_off = 0; }
    else           { mode = 1; mtile = tile - 32; A = log_vec;  w_off = NEWS_; }
    int n_base = nh * 128;

    int lrow = tid >> 3;
    int lf4  = tid & 7;
    const float* Abase = A  + (size_t)(mtile * 128 + lrow) * IN_ + lf4 * 4;
    const float* Wbase = W1 + (size_t)(n_base + lrow) * W1COLS_ + w_off + lf4 * 4;

    const float* posA[4];
    #pragma unroll
    for (int p = 0; p < 4; p++) {
        if (mode == 0) {
            posA[p] = pos_emb + lf4 * 4;
        } else {
            int r = mtile * 128 + p * 32 + lrow;
            posA[p] = pos_emb + (size_t)(1 + (r % HL_)) * POS_ + lf4 * 4;
        }
    }

    float acc[4][4][4];
    #pragma unroll
    for (int i = 0; i < 4; i++)
        #pragma unroll
        for (int j = 0; j < 4; j++)
            #pragma unroll
            for (int k = 0; k < 4; k++) acc[i][j][k] = 0.f;

    float4 aReg[4], wReg[4];
    #pragma unroll
    for (int p = 0; p < 4; p++) {
        aReg[p] = *(const float4*)(Abase + (size_t)p * 32 * IN_);
        wReg[p] = *(const float4*)(Wbase + (size_t)p * 32 * W1COLS_);
    }

    for (int kt = 0; kt < NKT; kt++) {
        #pragma unroll
        for (int p = 0; p < 4; p++) {
            uint32_t* as = &As[(p * 32 + lrow) * LDT + lf4 * 4];
            as[0] = to_tf32(aReg[p].x); as[1] = to_tf32(aReg[p].y);
            as[2] = to_tf32(aReg[p].z); as[3] = to_tf32(aReg[p].w);
            uint32_t* ws = &Ws[(p * 32 + lrow) * LDT + lf4 * 4];
            ws[0] = to_tf32(wReg[p].x); ws[1] = to_tf32(wReg[p].y);
            ws[2] = to_tf32(wReg[p].z); ws[3] = to_tf32(wReg[p].w);
        }
        __syncthreads();

        if (kt + 1 < NKT) {
            int t = kt + 1;
            if (t < IN_ / BK) {
                const float* An = Abase + t * BK;
                #pragma unroll
                for (int p = 0; p < 4; p++)
                    aReg[p] = *(const float4*)(An + (size_t)p * 32 * IN_);
            } else {
                int off = (t - IN_ / BK) * BK;
                #pragma unroll
                for (int p = 0; p < 4; p++)
                    aReg[p] = *(const float4*)(posA[p] + off);
            }
            const float* Wn = Wbase + t * BK;
            #pragma unroll
            for (int p = 0; p < 4; p++)
                wReg[p] = *(const float4*)(Wn + (size_t)p * 32 * W1COLS_);
        }

        #pragma unroll
        for (int kk = 0; kk < BK; kk += 8) {
            uint32_t afr[4][4], bfr[4][2];
            #pragma unroll
            for (int mf = 0; mf < 4; mf++) {
                int r0 = (wm * 64 + mf * 16 + gid) * LDT + kk + tig;
                afr[mf][0] = As[r0];
                afr[mf][1] = As[r0 + 8 * LDT];
                afr[mf][2] = As[r0 + 4];
                afr[mf][3] = As[r0 + 8 * LDT + 4];
            }
            #pragma unroll
            for (int nf = 0; nf < 4; nf++) {
                int c0 = (wn * 32 + nf * 8 + gid) * LDT + kk + tig;
                bfr[nf][0] = Ws[c0];
                bfr[nf][1] = Ws[c0 + 4];
            }
            #pragma unroll
            for (int mf = 0; mf < 4; mf++)
                #pragma unroll
                for (int nf = 0; nf < 4; nf++)
                    mma_tf32(acc[mf][nf], afr[mf], bfr[nf]);
        }
        __syncthreads();
    }

    float* outp = (mode == 0) ? g_pn : g_pl;
    #pragma unroll
    for (int mf = 0; mf < 4; mf++) {
        int r0 = mtile * 128 + wm * 64 + mf * 16 + gid;
        int r1 = r0 + 8;
        #pragma unroll
        for (int nf = 0; nf < 4; nf++) {
            int c = n_base + wn * 32 + nf * 8 + 2 * tig;
            float bx0 = 0.f, bx1 = 0.f;
            if (mode == 0) { bx0 = b1[c]; bx1 = b1[c + 1]; }
            float2 v0, v1;
            v0.x = acc[mf][nf][0] + bx0;
            v0.y = acc[mf][nf][1] + bx1;
            v1.x = acc[mf][nf][2] + bx0;
            v1.y = acc[mf][nf][3] + bx1;
            *(float2*)(outp + (size_t)r0 * ATT_ + c) = v0;
            *(float2*)(outp + (size_t)r1 * ATT_ + c) = v1;
        }
    }
}

// ---------------------------------------------------------------------------
// Kernel C: FUSED mask-compact + attn + out (R11 phase-B form).
// nf write hoisted to top; phase-C k-loop trimmed to active cnt.
// ---------------------------------------------------------------------------
#define FUSE_SMEM ((50 * 256 + 16 * 52 + 64 + 4) * 4)
__global__ __launch_bounds__(448, 2) void fused_kernel(
    const float* __restrict__ log_vec,
    const float* __restrict__ news_vec,
    const float* __restrict__ pos_emb,
    const int*   __restrict__ log_mask,
    const float* __restrict__ W2,
    const float* __restrict__ b2,
    float* __restrict__ out,
    float* __restrict__ nf_out)
{
    extern __shared__ float sm[];
    float* pl_s   = sm;                        // 50*256
    float* attn_s = sm + 50 * 256;             // 16*52 (zero-padded)
    int*   act_s  = (int*)(sm + 50 * 256 + 16 * 52);   // 52 (padded 64)
    int*   meta_s = act_s + 64;                 // cnt, unif

    int tid  = threadIdx.x;
    int b    = blockIdx.x >> 2;
    int q    = blockIdx.x & 3;
    int warp = tid >> 5, lane = tid & 31;
    int d    = tid;                             // 0..447
    bool lowd = (d < IN_);

    // ---- nf write FIRST: independent stream, overlaps everything below ----
    {
        int rbase = b * NN_ + q * 16;
        float posv = lowd ? 0.f : pos_emb[d - IN_];
        #pragma unroll 4
        for (int r = 0; r < 16; r++) {
            int gr = rbase + r;
            nf_out[(size_t)gr * NEWS_ + d] =
                lowd ? news_vec[(size_t)gr * IN_ + d] : posv;
        }
    }

    // mask compaction (warp 0, ballots)
    if (warp == 0) {
        int m1 = log_mask[b * HL_ + lane] != 0;
        int m2 = (lane < HL_ - 32) ? (log_mask[b * HL_ + 32 + lane] != 0) : 0;
        unsigned bb0 = __ballot_sync(0xffffffffu, m1);
        unsigned bb1 = __ballot_sync(0xffffffffu, m2);
        int cnt = __popc(bb0) + __popc(bb1);
        if (cnt == 0) {
            act_s[lane] = lane;
            if (lane < HL_ - 32) act_s[32 + lane] = 32 + lane;
            if (lane == 0) { meta_s[0] = HL_; meta_s[1] = 1; }
        } else {
            if (m1) act_s[__popc(bb0 & ((1u << lane) - 1u))] = lane;
            if (m2) act_s[__popc(bb0) + __popc(bb1 & ((1u << lane) - 1u))] = 32 + lane;
            if (lane == 0) { meta_s[0] = cnt; meta_s[1] = 0; }
        }
    }
    __syncthreads();
    int cnt  = meta_s[0];
    int unif = meta_s[1];

    // stage compact pl
    {
        int npl = cnt * 64;
        const float4* plg = (const float4*)(g_pl + (size_t)b * HL_ * ATT_);
        for (int i = tid; i < npl; i += 448) {
            int j = i >> 6, r = i & 63;
            ((float4*)pl_s)[j * 64 + r] = plg[(size_t)act_s[j] * 64 + r];
        }
    }
    float w2r[8];
    #pragma unroll
    for (int k = 0; k < 8; k++) w2r[k] = W2[lane + 32 * k];
    float bias2 = b2[0];
    __syncthreads();

    // ---- Phase B: attn rows -> attn_s. warps 0..13, n = warp (+14) ----
    for (int nn = warp; nn < 16; nn += 14) {
        int bn = b * NN_ + q * 16 + nn;
        float pnr[8];
        #pragma unroll
        for (int k = 0; k < 8; k++) pnr[k] = g_pn[(size_t)bn * ATT_ + lane + 32 * k];

        float* arow = attn_s + nn * 52;
        if (!unif) {
            float v0 = -3.0e38f, v1 = -3.0e38f;
            int jj = 0;
            for (; jj + 1 < cnt; jj += 2) {
                const float* p0 = pl_s + jj * ATT_;
                const float* p1 = pl_s + (jj + 1) * ATT_;
                float s0 = 0.f, s1 = 0.f;
                #pragma unroll
                for (int k = 0; k < 8; k++) {
                    s0 += tanh_fast(pnr[k] + p0[lane + 32 * k]) * w2r[k];
                    s1 += tanh_fast(pnr[k] + p1[lane + 32 * k]) * w2r[k];
                }
                #pragma unroll
                for (int o = 16; o > 0; o >>= 1) {
                    s0 += __shfl_xor_sync(0xffffffffu, s0, o);
                    s1 += __shfl_xor_sync(0xffffffffu, s1, o);
                }
                if (jj < 32)      { if (lane == jj)      v0 = s0 + bias2; }
                else              { if (lane == jj - 32) v1 = s0 + bias2; }
                int j2 = jj + 1;
                if (j2 < 32)      { if (lane == j2)      v0 = s1 + bias2; }
                else              { if (lane == j2 - 32) v1 = s1 + bias2; }
            }
            if (jj < cnt) {
                const float* p0 = pl_s + jj * ATT_;
                float s0 = 0.f;
                #pragma unroll
                for (int k = 0; k < 8; k++)
                    s0 += tanh_fast(pnr[k] + p0[lane + 32 * k]) * w2r[k];
                #pragma unroll
                for (int o = 16; o > 0; o >>= 1)
                    s0 += __shfl_xor_sync(0xffffffffu, s0, o);
                if (jj < 32)      { if (lane == jj)      v0 = s0 + bias2; }
                else              { if (lane == jj - 32) v1 = s0 + bias2; }
            }
            float mx = fmaxf(v0, v1);
            #pragma unroll
            for (int o = 16; o > 0; o >>= 1)
                mx = fmaxf(mx, __shfl_xor_sync(0xffffffffu, mx, o));
            float e0 = __expf(v0 - mx), e1 = __expf(v1 - mx);
            float sv = e0 + e1;
            #pragma unroll
            for (int o = 16; o > 0; o >>= 1)
                sv += __shfl_xor_sync(0xffffffffu, sv, o);
            float inv = 1.f / sv;
            arow[lane] = (lane < cnt) ? e0 * inv : 0.f;
            if (lane < 20) arow[lane + 32] = (lane + 32 < cnt) ? e1 * inv : 0.f;
        } else {
            float u = 1.f / HL_;
            arow[lane] = (lane < cnt) ? u : 0.f;
            if (lane < 20) arow[lane + 32] = (lane + 32 < cnt) ? u : 0.f;
        }
    }
    __syncthreads();

    // ---- Phase C: lf gather (spill-free) + weighted sum, trimmed to cnt ----
    float lf_reg[52];
    {
        const float* lv = log_vec + (size_t)b * HL_ * IN_ + d;
        const float* pe = pos_emb + POS_ + (d - IN_);
        #pragma unroll
        for (int j = 0; j < 52; j++) {
            float v = 0.f;
            if (j < cnt) {
                int h = act_s[j];
                v = lowd ? lv[(size_t)h * IN_] : pe[(size_t)h * POS_];
            }
            lf_reg[j] = v;
        }
    }

    {
        int kc = (cnt + 3) >> 2;                  // active float4 groups
        const float4* at4 = (const float4*)attn_s;
        float* obase = out + ((size_t)(b * NN_ + q * 16)) * NEWS_ + d;
        #pragma unroll 2
        for (int i = 0; i < 16; i++) {
            float4 a4acc = make_float4(0.f, 0.f, 0.f, 0.f);
            #pragma unroll
            for (int k = 0; k < 13; k++) {
                if (k >= kc) break;               // trailing groups are exact zeros
                float4 a4 = at4[i * 13 + k];
                a4acc.x += a4.x * lf_reg[4 * k];
                a4acc.y += a4.y * lf_reg[4 * k + 1];
                a4acc.z += a4.z * lf_reg[4 * k + 2];
                a4acc.w += a4.w * lf_reg[4 * k + 3];
            }
            obase[(size_t)i * NEWS_] = (a4acc.x + a4acc.y) + (a4acc.z + a4acc.w);
        }
    }
}

// ---------------------------------------------------------------------------
extern "C" void kernel_launch(void* const* d_in, const int* in_sizes, int n_in,
                              void* d_out, int out_size)
{
    const float* log_vec  = (const float*)d_in[0];
    const int*   log_mask = (const int*)  d_in[1];
    const float* news_vec = (const float*)d_in[2];
    const float* pos_emb  = (const float*)d_in[3];
    const float* W1       = (const float*)d_in[4];
    const float* b1       = (const float*)d_in[5];
    const float* W2       = (const float*)d_in[6];
    const float* b2       = (const float*)d_in[7];
    float* out = (float*)d_out;

    const int NF_TOTAL = B_ * NN_ * NEWS_;
    cudaFuncSetAttribute(fused_kernel, cudaFuncAttributeMaxDynamicSharedMemorySize, FUSE_SMEM);

    gemm_mma_kernel<<<114, 256>>>(news_vec, log_vec, pos_emb, b1, W1);
    fused_kernel<<<B_ * 4, 448, FUSE_SMEM>>>(log_vec, news_vec, pos_emb, log_mask,
                                             W2, b2, out, out + NF_TOTAL);
}